// round 10
// baseline (speedup 1.0000x reference)
#include <cuda_runtime.h>
#include <cuda_fp16.h>
#include <cstdint>

// ---------------------------------------------------------------------------
// GraphSAGE layer on GB300 (sm_103 baseline -> mma.sync fp16/fp32-acc)
// CSR build + FUSED gather+GEMM: each GEMM CTA gathers its own 128 agg rows
// into SMEM (no agg gmem round-trip).
//   out = relu( x @ Ws^T + mean_nbr(x) @ Wn^T + bias )
// N = 100000, in_dim = out_dim = 128, E = 800000 undirected (1.6M directed)
// ---------------------------------------------------------------------------

#define MAXN 100000
#define MAXE 800000
#define DIM  128

__device__ __align__(16) __half g_xh [(size_t)MAXN * DIM];   // fp16 x
__device__ __align__(16) __half g_wh [128 * 256];            // fused [Ws|Wn]
__device__ int g_degI[MAXN];
__device__ int g_rowStart[MAXN];
__device__ int g_nbr[2 * MAXE];
__device__ int g_slotS[MAXE];
__device__ int g_slotD[MAXE];
__device__ int g_cursor;
__device__ int g_is64;

__device__ __forceinline__ uint32_t h2_to_u32(__half2 h) {
    uint32_t u;
    *reinterpret_cast<__half2*>(&u) = h;
    return u;
}
__device__ __forceinline__ __half2 u32_to_h2(uint32_t u) {
    return *reinterpret_cast<__half2*>(&u);
}
__device__ __forceinline__ uint32_t smem_u32(const void* p) {
    return (uint32_t)__cvta_generic_to_shared(p);
}
__device__ __forceinline__ void cp16(uint32_t dst, const void* src, bool pred) {
    int sz = pred ? 16 : 0;
    asm volatile("cp.async.cg.shared.global [%0], [%1], 16, %2;"
                 :: "r"(dst), "l"(src), "r"(sz) : "memory");
}

// ---------------------------------------------------------------------------
// Kernel A: zero degI + cursor, probe edge dtype
// ---------------------------------------------------------------------------
__global__ void init_probe_kernel(const long long* __restrict__ ei64,
                                  int n_deg, long long N) {
    int i = blockIdx.x * blockDim.x + threadIdx.x;
    int stride = gridDim.x * blockDim.x;
    if (i == 0) {
        int is64 = 1;
#pragma unroll
        for (int k = 0; k < 4; k++)
            if ((unsigned long long)ei64[k] >= (unsigned long long)N) is64 = 0;
        g_is64 = is64;
        g_cursor = 0;
    }
    for (int k = i; k < n_deg; k += stride) g_degI[k] = 0;
}

__device__ __forceinline__ bool load_edge(const void* ei_raw, int E, int N,
                                          int e, int& s, int& d) {
    long long sl, dl;
    if (g_is64) {
        const long long* ei = (const long long*)ei_raw;
        sl = ei[e]; dl = ei[(size_t)E + e];
    } else {
        const int* ei = (const int*)ei_raw;
        sl = ei[e]; dl = ei[(size_t)E + e];
    }
    if ((unsigned long long)sl >= (unsigned long long)N ||
        (unsigned long long)dl >= (unsigned long long)N) return false;
    s = (int)sl; d = (int)dl;
    return true;
}

// ---------------------------------------------------------------------------
// Kernel B: count degrees (slots via atomic returns) + fp16 convert
// ---------------------------------------------------------------------------
__global__ void count_convert_kernel(const void* __restrict__ ei_raw,
                                     const float* __restrict__ x,
                                     const float* __restrict__ Ws,
                                     const float* __restrict__ Wn,
                                     int E, int N) {
    int gid = blockIdx.x * blockDim.x + threadIdx.x;
    int stride = gridDim.x * blockDim.x;

    for (int e = gid; e < E; e += stride) {
        int s, d;
        if (!load_edge(ei_raw, E, N, e, s, d)) { g_slotS[e] = -1; continue; }
        g_slotS[e] = atomicAdd(&g_degI[s], 1);
        g_slotD[e] = atomicAdd(&g_degI[d], 1);
    }

    const float4* x4 = reinterpret_cast<const float4*>(x);
    uint2* xh = reinterpret_cast<uint2*>(g_xh);
    int total = N * (DIM / 4);
    for (int k = gid; k < total; k += stride) {
        float4 v = x4[k];
        uint2 o;
        o.x = h2_to_u32(__floats2half2_rn(v.x, v.y));
        o.y = h2_to_u32(__floats2half2_rn(v.z, v.w));
        xh[k] = o;
    }

    uint2* wh = reinterpret_cast<uint2*>(g_wh);
    int wtotal = 128 * 256 / 4;
    for (int k = gid; k < wtotal; k += stride) {
        int n = (k * 4) >> 8;
        int c = (k * 4) & 255;
        const float* W = (c < 128) ? (Ws + (size_t)n * 128 + c)
                                   : (Wn + (size_t)n * 128 + (c - 128));
        float4 v = *reinterpret_cast<const float4*>(W);
        uint2 o;
        o.x = h2_to_u32(__floats2half2_rn(v.x, v.y));
        o.y = h2_to_u32(__floats2half2_rn(v.z, v.w));
        wh[k] = o;
    }
}

// ---------------------------------------------------------------------------
// Kernel C: allocate segments — warp-aggregated scan
// ---------------------------------------------------------------------------
__global__ void alloc_kernel(int N) {
    int i = blockIdx.x * blockDim.x + threadIdx.x;
    int lane = threadIdx.x & 31;
    int deg = (i < N) ? g_degI[i] : 0;
    int sum = deg;
#pragma unroll
    for (int off = 1; off < 32; off <<= 1) {
        int v = __shfl_up_sync(0xFFFFFFFF, sum, off);
        if (lane >= off) sum += v;
    }
    int total = __shfl_sync(0xFFFFFFFF, sum, 31);
    int base = 0;
    if (lane == 31) base = atomicAdd(&g_cursor, total);
    base = __shfl_sync(0xFFFFFFFF, base, 31);
    if (i < N) g_rowStart[i] = base + sum - deg;
}

// ---------------------------------------------------------------------------
// Kernel D: fill adjacency — no atomics
// ---------------------------------------------------------------------------
__global__ void fill_kernel(const void* __restrict__ ei_raw, int E, int N) {
    int e = blockIdx.x * blockDim.x + threadIdx.x;
    if (e >= E) return;
    int ps = g_slotS[e];
    if (ps < 0) return;
    int s, d;
    (void)load_edge(ei_raw, E, N, e, s, d);
    int pd = g_slotD[e];
    g_nbr[g_rowStart[s] + ps] = d;
    g_nbr[g_rowStart[d] + pd] = s;
}

// ---------------------------------------------------------------------------
// Kernel E: FUSED gather + fp16 GEMM.
// Phase 1: cp.async the full 128x128 x-tile (4 chunks) + B chunk 0, then each
//          warp gathers 16 nodes' agg rows into SMEM Ag (fp32 accum -> fp16).
// Phase 2: 8 MMA chunks; A = As[c] (c<4) or Ag[c-4] (c>=4); B double-buffered.
// SMEM: As 40KB + Ag 40KB + Bs 20KB = 100KB dynamic -> 2 CTAs/SM.
// ---------------------------------------------------------------------------
#define LDH 20
#define CHS (128 * LDH)   // uint32 per chunk-tile

__device__ __forceinline__ void mma_f16(float* c, const uint32_t* a, const uint32_t* b) {
    asm volatile(
        "mma.sync.aligned.m16n8k16.row.col.f32.f16.f16.f32 "
        "{%0,%1,%2,%3}, {%4,%5,%6,%7}, {%8,%9}, {%0,%1,%2,%3};"
        : "+f"(c[0]), "+f"(c[1]), "+f"(c[2]), "+f"(c[3])
        : "r"(a[0]), "r"(a[1]), "r"(a[2]), "r"(a[3]), "r"(b[0]), "r"(b[1]));
}

__global__ __launch_bounds__(256) void gemm_fused_kernel(
    const float* __restrict__ bias,
    float* __restrict__ out,
    int N)
{
    extern __shared__ uint32_t smem[];
    uint32_t* As = smem;              // [4][128][LDH]
    uint32_t* Ag = smem + 4 * CHS;    // [4][128][LDH]
    uint32_t* Bs = smem + 8 * CHS;    // [2][128][LDH]

    int tid  = threadIdx.x;
    int wid  = tid >> 5;
    int lane = tid & 31;
    int g    = lane >> 2;
    int t    = lane & 3;
    int wm   = wid >> 2;
    int wn   = wid & 3;
    int r0   = blockIdx.x * 128;

    // ---- issue full x tile (4 chunks, 2048 uint4 slots) + B chunk 0 ----
#pragma unroll
    for (int i = 0; i < 8; i++) {
        int idx  = tid + 256 * i;          // 0..2047
        int c    = idx >> 9;               // chunk 0..3
        int rest = idx & 511;
        int r    = rest >> 2;
        int q4   = rest & 3;
        int node = r0 + r;
        int kh   = c * 32 + q4 * 8;        // < 128 -> x region
        cp16(smem_u32(&As[c * CHS + r * LDH + q4 * 4]),
             g_xh + (size_t)node * DIM + kh, node < N);
    }
#pragma unroll
    for (int i = 0; i < 2; i++) {
        int idx = tid + 256 * i;
        int r   = idx >> 2;
        int q4  = idx & 3;
        cp16(smem_u32(&Bs[r * LDH + q4 * 4]),
             g_wh + (size_t)r * 256 + q4 * 8, true);
    }
    asm volatile("cp.async.commit_group;" ::: "memory");

    // ---- gather phase: warp wid handles rows wid*16 .. wid*16+15 ----
    const uint2* xh2 = reinterpret_cast<const uint2*>(g_xh);
    for (int j = 0; j < 16; j++) {
        int r    = wid * 16 + j;
        int node = r0 + r;
        float4 acc = make_float4(0.f, 0.f, 0.f, 0.f);
        float inv = 0.f;
        if (node < N) {
            int start = g_rowStart[node];
            int deg   = g_degI[node];
            int end   = start + deg;
            int p = start;
            for (; p + 8 <= end; p += 8) {
                int nn[8];
#pragma unroll
                for (int u = 0; u < 8; u++) nn[u] = g_nbr[p + u];
                uint2 v[8];
#pragma unroll
                for (int u = 0; u < 8; u++) v[u] = xh2[(size_t)nn[u] * 32 + lane];
#pragma unroll
                for (int u = 0; u < 8; u++) {
                    float2 f0 = __half22float2(u32_to_h2(v[u].x));
                    float2 f1 = __half22float2(u32_to_h2(v[u].y));
                    acc.x += f0.x; acc.y += f0.y; acc.z += f1.x; acc.w += f1.y;
                }
            }
            for (; p < end; p++) {
                uint2 v = xh2[(size_t)g_nbr[p] * 32 + lane];
                float2 f0 = __half22float2(u32_to_h2(v.x));
                float2 f1 = __half22float2(u32_to_h2(v.y));
                acc.x += f0.x; acc.y += f0.y; acc.z += f1.x; acc.w += f1.y;
            }
            inv = 1.0f / fmaxf((float)deg, 1.0f);
        }
        uint32_t u0 = h2_to_u32(__floats2half2_rn(acc.x * inv, acc.y * inv));
        uint32_t u1 = h2_to_u32(__floats2half2_rn(acc.z * inv, acc.w * inv));
        int col = 2 * lane;                // uint32 col 0..62
        int cc  = col >> 4;                // agg chunk 0..3
        int q   = col & 15;
        Ag[cc * CHS + r * LDH + q]     = u0;
        Ag[cc * CHS + r * LDH + q + 1] = u1;
    }
    __syncthreads();   // Ag complete

    // ---- accumulators ----
    float acc[4][4][4];
#pragma unroll
    for (int mf = 0; mf < 4; mf++)
#pragma unroll
        for (int nf = 0; nf < 4; nf++)
#pragma unroll
            for (int i = 0; i < 4; i++) acc[mf][nf][i] = 0.f;

    // ---- MMA main loop ----
    for (int c = 0; c < 8; c++) {
        int buf = c & 1;
        if (c < 7) {
            int cn = c + 1;
#pragma unroll
            for (int i = 0; i < 2; i++) {
                int idx = tid + 256 * i;
                int r   = idx >> 2;
                int q4  = idx & 3;
                cp16(smem_u32(&Bs[(buf ^ 1) * CHS + r * LDH + q4 * 4]),
                     g_wh + (size_t)r * 256 + cn * 32 + q4 * 8, true);
            }
            asm volatile("cp.async.commit_group;" ::: "memory");
            asm volatile("cp.async.wait_group 1;" ::: "memory");
        } else {
            asm volatile("cp.async.wait_group 0;" ::: "memory");
        }
        __syncthreads();

        const uint32_t* Ab = (c < 4) ? (As + c * CHS) : (Ag + (c - 4) * CHS);
        const uint32_t* Bb = Bs + buf * CHS;

#pragma unroll
        for (int s = 0; s < 2; s++) {
            int k0 = s * 8;
            uint32_t a[4][4];
#pragma unroll
            for (int mf = 0; mf < 4; mf++) {
                int m0 = wm * 64 + mf * 16;
                a[mf][0] = Ab[(m0 + g) * LDH + k0 + t];
                a[mf][1] = Ab[(m0 + g + 8) * LDH + k0 + t];
                a[mf][2] = Ab[(m0 + g) * LDH + k0 + t + 4];
                a[mf][3] = Ab[(m0 + g + 8) * LDH + k0 + t + 4];
            }
            uint32_t b[4][2];
#pragma unroll
            for (int nf = 0; nf < 4; nf++) {
                int n0 = wn * 32 + nf * 8;
                b[nf][0] = Bb[(n0 + g) * LDH + k0 + t];
                b[nf][1] = Bb[(n0 + g) * LDH + k0 + t + 4];
            }
#pragma unroll
            for (int mf = 0; mf < 4; mf++)
#pragma unroll
                for (int nf = 0; nf < 4; nf++)
                    mma_f16(acc[mf][nf], a[mf], b[nf]);
        }
        __syncthreads();   // Bs[buf] reuse barrier
    }

    // ---- epilogue: bias + relu (fp32 out) ----
#pragma unroll
    for (int mf = 0; mf < 4; mf++) {
        int rA = r0 + wm * 64 + mf * 16 + g;
        int rB = rA + 8;
#pragma unroll
        for (int nf = 0; nf < 4; nf++) {
            int col = wn * 32 + nf * 8 + 2 * t;
            float2 bv = *reinterpret_cast<const float2*>(bias + col);
            if (rA < N) {
                float2 o;
                o.x = fmaxf(acc[mf][nf][0] + bv.x, 0.f);
                o.y = fmaxf(acc[mf][nf][1] + bv.y, 0.f);
                *reinterpret_cast<float2*>(out + (size_t)rA * DIM + col) = o;
            }
            if (rB < N) {
                float2 o;
                o.x = fmaxf(acc[mf][nf][2] + bv.x, 0.f);
                o.y = fmaxf(acc[mf][nf][3] + bv.y, 0.f);
                *reinterpret_cast<float2*>(out + (size_t)rB * DIM + col) = o;
            }
        }
    }
}

// ---------------------------------------------------------------------------
// Launch
// ---------------------------------------------------------------------------
#define FUSED_SMEM (10 * CHS * 4)   // 10 chunk-tiles * 2560 u32 * 4B = 102400

extern "C" void kernel_launch(void* const* d_in, const int* in_sizes, int n_in,
                              void* d_out, int out_size) {
    const float* x  = (const float*)d_in[0];
    const void*  ei = d_in[1];

    int N = in_sizes[0] / DIM;          // 100000
    int E = in_sizes[1] / 2;            // 800000

    int iW = (n_in >= 6 && in_sizes[2] == 1) ? 3 : 2;
    const float* Ws   = (const float*)d_in[iW];
    const float* Wn   = (const float*)d_in[iW + 1];
    const float* bias = (const float*)d_in[iW + 2];
    float* out = (float*)d_out;

    cudaFuncSetAttribute(gemm_fused_kernel,
                         cudaFuncAttributeMaxDynamicSharedMemorySize, FUSED_SMEM);

    init_probe_kernel<<<512, 256>>>((const long long*)ei, N, (long long)N);

    count_convert_kernel<<<4096, 256>>>(ei, x, Ws, Wn, E, N);

    alloc_kernel<<<(N + 255) / 256, 256>>>(N);

    int eblocks = (E + 255) / 256;
    fill_kernel<<<eblocks, 256>>>(ei, E, N);

    int gblocks = (N + 127) / 128;
    gemm_fused_kernel<<<gblocks, 256, FUSED_SMEM>>>(bias, out, N);
}

// round 11
// speedup vs baseline: 1.3609x; 1.3609x over previous
#include <cuda_runtime.h>
#include <cuda_fp16.h>
#include <cstdint>

// ---------------------------------------------------------------------------
// GraphSAGE layer on GB300 (sm_103 baseline -> mma.sync fp16/fp32-acc)
// CSR two-phase aggregation over fp16 features + cp.async-pipelined fp16 GEMM.
//   agg[i] = mean over neighbors (bidirectional) of x
//   out = relu( x @ Ws^T + agg @ Wn^T + bias )   (fp32 out)
// N = 100000, in_dim = out_dim = 128, E = 800000 undirected (1.6M directed)
// ---------------------------------------------------------------------------

#define MAXN 100000
#define MAXE 800000
#define DIM  128

__device__ __align__(16) __half g_xh [(size_t)MAXN * DIM];   // fp16 x
__device__ __align__(16) __half g_ah [(size_t)MAXN * DIM];   // fp16 agg (normalized)
__device__ __align__(16) __half g_wh [128 * 256];            // fused [Ws|Wn]
__device__ int g_degI[MAXN];
__device__ int g_rowStart[MAXN];
__device__ int g_nbr[2 * MAXE];
__device__ int g_slotS[MAXE];
__device__ int g_slotD[MAXE];
__device__ int g_cursor;
__device__ int g_is64;

__device__ __forceinline__ uint32_t h2_to_u32(__half2 h) {
    uint32_t u;
    *reinterpret_cast<__half2*>(&u) = h;
    return u;
}
__device__ __forceinline__ __half2 u32_to_h2(uint32_t u) {
    return *reinterpret_cast<__half2*>(&u);
}
__device__ __forceinline__ uint32_t smem_u32(const void* p) {
    return (uint32_t)__cvta_generic_to_shared(p);
}
__device__ __forceinline__ void cp16(uint32_t dst, const void* src, bool pred) {
    int sz = pred ? 16 : 0;
    asm volatile("cp.async.cg.shared.global [%0], [%1], 16, %2;"
                 :: "r"(dst), "l"(src), "r"(sz) : "memory");
}

// ---------------------------------------------------------------------------
// Kernel A: zero degI + cursor, probe edge dtype (JAX may emit int32/int64)
// ---------------------------------------------------------------------------
__global__ void init_probe_kernel(const long long* __restrict__ ei64,
                                  int n_deg, long long N) {
    int i = blockIdx.x * blockDim.x + threadIdx.x;
    int stride = gridDim.x * blockDim.x;
    if (i == 0) {
        int is64 = 1;
#pragma unroll
        for (int k = 0; k < 4; k++)
            if ((unsigned long long)ei64[k] >= (unsigned long long)N) is64 = 0;
        g_is64 = is64;
        g_cursor = 0;
    }
    for (int k = i; k < n_deg; k += stride) g_degI[k] = 0;
}

__device__ __forceinline__ bool load_edge(const void* ei_raw, int E, int N,
                                          int e, int& s, int& d) {
    long long sl, dl;
    if (g_is64) {
        const long long* ei = (const long long*)ei_raw;
        sl = ei[e]; dl = ei[(size_t)E + e];
    } else {
        const int* ei = (const int*)ei_raw;
        sl = ei[e]; dl = ei[(size_t)E + e];
    }
    if ((unsigned long long)sl >= (unsigned long long)N ||
        (unsigned long long)dl >= (unsigned long long)N) return false;
    s = (int)sl; d = (int)dl;
    return true;
}

// ---------------------------------------------------------------------------
// Kernel B: count degrees + fp16 convert, BLOCK-PARTITIONED so the
// atomic-bound edge pass and the bandwidth-bound convert pass run on
// different SMs concurrently (per-thread phase serialization was a no-op).
// Blocks [0, EDGE_BLOCKS) count edges; the rest convert x and W.
// ---------------------------------------------------------------------------
#define CC_BLOCKS   4096
#define EDGE_BLOCKS 2560

__global__ void count_convert_kernel(const void* __restrict__ ei_raw,
                                     const float* __restrict__ x,
                                     const float* __restrict__ Ws,
                                     const float* __restrict__ Wn,
                                     int E, int N) {
    int tid = threadIdx.x;

    if (blockIdx.x < EDGE_BLOCKS) {
        // --- edge counting partition ---
        int gid = blockIdx.x * blockDim.x + tid;
        int stride = EDGE_BLOCKS * blockDim.x;
        for (int e = gid; e < E; e += stride) {
            int s, d;
            if (!load_edge(ei_raw, E, N, e, s, d)) { g_slotS[e] = -1; continue; }
            g_slotS[e] = atomicAdd(&g_degI[s], 1);
            g_slotD[e] = atomicAdd(&g_degI[d], 1);
        }
    } else {
        // --- convert partition ---
        int gid = (blockIdx.x - EDGE_BLOCKS) * blockDim.x + tid;
        int stride = (CC_BLOCKS - EDGE_BLOCKS) * blockDim.x;

        const float4* x4 = reinterpret_cast<const float4*>(x);
        uint2* xh = reinterpret_cast<uint2*>(g_xh);
        int total = N * (DIM / 4);
        for (int k = gid; k < total; k += stride) {
            float4 v = x4[k];
            uint2 o;
            o.x = h2_to_u32(__floats2half2_rn(v.x, v.y));
            o.y = h2_to_u32(__floats2half2_rn(v.z, v.w));
            xh[k] = o;
        }

        uint2* wh = reinterpret_cast<uint2*>(g_wh);
        int wtotal = 128 * 256 / 4;
        for (int k = gid; k < wtotal; k += stride) {
            int n = (k * 4) >> 8;
            int c = (k * 4) & 255;
            const float* W = (c < 128) ? (Ws + (size_t)n * 128 + c)
                                       : (Wn + (size_t)n * 128 + (c - 128));
            float4 v = *reinterpret_cast<const float4*>(W);
            uint2 o;
            o.x = h2_to_u32(__floats2half2_rn(v.x, v.y));
            o.y = h2_to_u32(__floats2half2_rn(v.z, v.w));
            wh[k] = o;
        }
    }
}

// ---------------------------------------------------------------------------
// Kernel C: allocate segments — block-aggregated scan, 1 atomic per block
// ---------------------------------------------------------------------------
__global__ void alloc_kernel(int N) {
    __shared__ int wsum[8];
    __shared__ int woff[8];
    __shared__ int sbase;

    int i = blockIdx.x * blockDim.x + threadIdx.x;
    int lane = threadIdx.x & 31;
    int wrp  = threadIdx.x >> 5;

    int deg = (i < N) ? g_degI[i] : 0;
    int sum = deg;
#pragma unroll
    for (int off = 1; off < 32; off <<= 1) {
        int v = __shfl_up_sync(0xFFFFFFFF, sum, off);
        if (lane >= off) sum += v;
    }
    if (lane == 31) wsum[wrp] = sum;
    __syncthreads();
    if (threadIdx.x == 0) {
        int run = 0;
#pragma unroll
        for (int w = 0; w < 8; w++) { woff[w] = run; run += wsum[w]; }
        sbase = atomicAdd(&g_cursor, run);
    }
    __syncthreads();
    if (i < N) g_rowStart[i] = sbase + woff[wrp] + sum - deg;
}

// ---------------------------------------------------------------------------
// Kernel D: fill adjacency — no atomics (slots precomputed)
// ---------------------------------------------------------------------------
__global__ void fill_kernel(const void* __restrict__ ei_raw, int E, int N) {
    int e = blockIdx.x * blockDim.x + threadIdx.x;
    if (e >= E) return;
    int ps = g_slotS[e];
    if (ps < 0) return;
    int s, d;
    (void)load_edge(ei_raw, E, N, e, s, d);
    int pd = g_slotD[e];
    g_nbr[g_rowStart[s] + ps] = d;
    g_nbr[g_rowStart[d] + pd] = s;
}

// ---------------------------------------------------------------------------
// Kernel E: gather on fp16 features. One warp per node; lane holds 4 halfs.
// ---------------------------------------------------------------------------
__global__ void gather_kernel(int N) {
    int warp = (blockIdx.x * blockDim.x + threadIdx.x) >> 5;
    int lane = threadIdx.x & 31;
    if (warp >= N) return;

    int start = g_rowStart[warp];
    int deg   = g_degI[warp];
    int end   = start + deg;

    const uint2* xh = reinterpret_cast<const uint2*>(g_xh);
    float4 acc = make_float4(0.f, 0.f, 0.f, 0.f);

    int j = start;
    for (; j + 8 <= end; j += 8) {
        int n[8];
#pragma unroll
        for (int u = 0; u < 8; u++) n[u] = g_nbr[j + u];
        uint2 v[8];
#pragma unroll
        for (int u = 0; u < 8; u++) v[u] = xh[(size_t)n[u] * 32 + lane];
#pragma unroll
        for (int u = 0; u < 8; u++) {
            float2 f0 = __half22float2(u32_to_h2(v[u].x));
            float2 f1 = __half22float2(u32_to_h2(v[u].y));
            acc.x += f0.x; acc.y += f0.y; acc.z += f1.x; acc.w += f1.y;
        }
    }
    for (; j < end; j++) {
        uint2 v = xh[(size_t)g_nbr[j] * 32 + lane];
        float2 f0 = __half22float2(u32_to_h2(v.x));
        float2 f1 = __half22float2(u32_to_h2(v.y));
        acc.x += f0.x; acc.y += f0.y; acc.z += f1.x; acc.w += f1.y;
    }

    float inv = 1.0f / fmaxf((float)deg, 1.0f);
    uint2 o;
    o.x = h2_to_u32(__floats2half2_rn(acc.x * inv, acc.y * inv));
    o.y = h2_to_u32(__floats2half2_rn(acc.z * inv, acc.w * inv));
    reinterpret_cast<uint2*>(g_ah)[(size_t)warp * 32 + lane] = o;
}

// ---------------------------------------------------------------------------
// Kernel F: fp16 mma.sync GEMM, cp.async double-buffered SMEM pipeline.
// out = relu([x_h | agg_h] @ W_h^T + bias)
// CTA: 128x128, K=256 in 8 chunks of 32 halfs. 8 warps = 2(m) x 4(n).
// ---------------------------------------------------------------------------
#define LDH 20

__device__ __forceinline__ void mma_f16(float* c, const uint32_t* a, const uint32_t* b) {
    asm volatile(
        "mma.sync.aligned.m16n8k16.row.col.f32.f16.f16.f32 "
        "{%0,%1,%2,%3}, {%4,%5,%6,%7}, {%8,%9}, {%0,%1,%2,%3};"
        : "+f"(c[0]), "+f"(c[1]), "+f"(c[2]), "+f"(c[3])
        : "r"(a[0]), "r"(a[1]), "r"(a[2]), "r"(a[3]), "r"(b[0]), "r"(b[1]));
}

__global__ __launch_bounds__(256) void gemm_mma_kernel(
    const float* __restrict__ bias,
    float* __restrict__ out,
    int N)
{
    __shared__ uint32_t As[2][128][LDH];
    __shared__ uint32_t Bs[2][128][LDH];

    int tid  = threadIdx.x;
    int wid  = tid >> 5;
    int lane = tid & 31;
    int g    = lane >> 2;
    int t    = lane & 3;
    int wm   = wid >> 2;
    int wn   = wid & 3;
    int r0   = blockIdx.x * 128;

    int arow[2], aq[2];
#pragma unroll
    for (int i = 0; i < 2; i++) {
        int idx = tid + 256 * i;
        arow[i] = idx >> 2;
        aq[i]   = idx & 3;
    }

    float acc[4][4][4];
#pragma unroll
    for (int mf = 0; mf < 4; mf++)
#pragma unroll
        for (int nf = 0; nf < 4; nf++)
#pragma unroll
            for (int i = 0; i < 4; i++) acc[mf][nf][i] = 0.f;

    auto issue = [&](int c, int buf) {
#pragma unroll
        for (int i = 0; i < 2; i++) {
            int node = r0 + arow[i];
            int kh = c * 32 + aq[i] * 8;
            const __half* srcA = (kh < DIM)
                ? (g_xh + (size_t)node * DIM + kh)
                : (g_ah + (size_t)node * DIM + (kh - DIM));
            cp16(smem_u32(&As[buf][arow[i]][aq[i] * 4]), srcA, node < N);
            cp16(smem_u32(&Bs[buf][arow[i]][aq[i] * 4]),
                 g_wh + (size_t)arow[i] * 256 + kh, true);
        }
    };

    issue(0, 0);
    asm volatile("cp.async.commit_group;" ::: "memory");

    for (int c = 0; c < 8; c++) {
        int buf = c & 1;
        if (c < 7) {
            issue(c + 1, buf ^ 1);
            asm volatile("cp.async.commit_group;" ::: "memory");
            asm volatile("cp.async.wait_group 1;" ::: "memory");
        } else {
            asm volatile("cp.async.wait_group 0;" ::: "memory");
        }
        __syncthreads();

#pragma unroll
        for (int s = 0; s < 2; s++) {
            int k0 = s * 8;
            uint32_t a[4][4];
#pragma unroll
            for (int mf = 0; mf < 4; mf++) {
                int m0 = wm * 64 + mf * 16;
                a[mf][0] = As[buf][m0 + g][k0 + t];
                a[mf][1] = As[buf][m0 + g + 8][k0 + t];
                a[mf][2] = As[buf][m0 + g][k0 + t + 4];
                a[mf][3] = As[buf][m0 + g + 8][k0 + t + 4];
            }
            uint32_t b[4][2];
#pragma unroll
            for (int nf = 0; nf < 4; nf++) {
                int n0 = wn * 32 + nf * 8;
                b[nf][0] = Bs[buf][n0 + g][k0 + t];
                b[nf][1] = Bs[buf][n0 + g][k0 + t + 4];
            }
#pragma unroll
            for (int mf = 0; mf < 4; mf++)
#pragma unroll
                for (int nf = 0; nf < 4; nf++)
                    mma_f16(acc[mf][nf], a[mf], b[nf]);
        }
        __syncthreads();
    }

    // ---- epilogue: bias + relu (fp32 out) ----
#pragma unroll
    for (int mf = 0; mf < 4; mf++) {
        int rA = r0 + wm * 64 + mf * 16 + g;
        int rB = rA + 8;
#pragma unroll
        for (int nf = 0; nf < 4; nf++) {
            int col = wn * 32 + nf * 8 + 2 * t;
            float2 bv = *reinterpret_cast<const float2*>(bias + col);
            if (rA < N) {
                float2 o;
                o.x = fmaxf(acc[mf][nf][0] + bv.x, 0.f);
                o.y = fmaxf(acc[mf][nf][1] + bv.y, 0.f);
                *reinterpret_cast<float2*>(out + (size_t)rA * DIM + col) = o;
            }
            if (rB < N) {
                float2 o;
                o.x = fmaxf(acc[mf][nf][2] + bv.x, 0.f);
                o.y = fmaxf(acc[mf][nf][3] + bv.y, 0.f);
                *reinterpret_cast<float2*>(out + (size_t)rB * DIM + col) = o;
            }
        }
    }
}

// ---------------------------------------------------------------------------
// Launch
// ---------------------------------------------------------------------------
extern "C" void kernel_launch(void* const* d_in, const int* in_sizes, int n_in,
                              void* d_out, int out_size) {
    const float* x  = (const float*)d_in[0];
    const void*  ei = d_in[1];

    int N = in_sizes[0] / DIM;          // 100000
    int E = in_sizes[1] / 2;            // 800000

    int iW = (n_in >= 6 && in_sizes[2] == 1) ? 3 : 2;
    const float* Ws   = (const float*)d_in[iW];
    const float* Wn   = (const float*)d_in[iW + 1];
    const float* bias = (const float*)d_in[iW + 2];
    float* out = (float*)d_out;

    init_probe_kernel<<<512, 256>>>((const long long*)ei, N, (long long)N);

    count_convert_kernel<<<CC_BLOCKS, 256>>>(ei, x, Ws, Wn, E, N);

    alloc_kernel<<<(N + 255) / 256, 256>>>(N);

    int eblocks = (E + 255) / 256;
    fill_kernel<<<eblocks, 256>>>(ei, E, N);

    gather_kernel<<<(N + 7) / 8, 256>>>(N);

    int gblocks = (N + 127) / 128;
    gemm_mma_kernel<<<gblocks, 256>>>(bias, out, N);
}

// round 12
// speedup vs baseline: 1.4696x; 1.0799x over previous
#include <cuda_runtime.h>
#include <cuda_fp16.h>
#include <cstdint>

// ---------------------------------------------------------------------------
// GraphSAGE layer on GB300 (sm_103 baseline -> mma.sync fp16/fp32-acc)
// Single-pass padded-CSR build + fp16 gather + cp.async-pipelined fp16 GEMM.
//   agg[i] = mean over neighbors (bidirectional) of x
//   out = relu( x @ Ws^T + agg @ Wn^T + bias )   (fp32 out)
// N = 100000, in_dim = out_dim = 128, E = 800000 undirected (1.6M directed)
// ---------------------------------------------------------------------------

#define MAXN 100000
#define MAXE 800000
#define DIM  128
#define CAP  64     // neighbor slots per node; deg ~ Poisson(16), P(>=64) ~ 1e-20

__device__ __align__(16) __half g_xh [(size_t)MAXN * DIM];   // fp16 x
__device__ __align__(16) __half g_ah [(size_t)MAXN * DIM];   // fp16 agg (normalized)
__device__ __align__(16) __half g_wh [128 * 256];            // fused [Ws|Wn]
__device__ int g_degI[MAXN];
__device__ int g_nbr[(size_t)MAXN * CAP];
__device__ int g_is64;

__device__ __forceinline__ uint32_t h2_to_u32(__half2 h) {
    uint32_t u;
    *reinterpret_cast<__half2*>(&u) = h;
    return u;
}
__device__ __forceinline__ __half2 u32_to_h2(uint32_t u) {
    return *reinterpret_cast<__half2*>(&u);
}
__device__ __forceinline__ uint32_t smem_u32(const void* p) {
    return (uint32_t)__cvta_generic_to_shared(p);
}
__device__ __forceinline__ void cp16(uint32_t dst, const void* src, bool pred) {
    int sz = pred ? 16 : 0;
    asm volatile("cp.async.cg.shared.global [%0], [%1], 16, %2;"
                 :: "r"(dst), "l"(src), "r"(sz) : "memory");
}

// ---------------------------------------------------------------------------
// Kernel A: zero deg, probe edge dtype (JAX may emit int32/int64)
// ---------------------------------------------------------------------------
__global__ void init_probe_kernel(const long long* __restrict__ ei64,
                                  int n_deg, long long N) {
    int i = blockIdx.x * blockDim.x + threadIdx.x;
    int stride = gridDim.x * blockDim.x;
    if (i == 0) {
        int is64 = 1;
#pragma unroll
        for (int k = 0; k < 4; k++)
            if ((unsigned long long)ei64[k] >= (unsigned long long)N) is64 = 0;
        g_is64 = is64;
    }
    for (int k = i; k < n_deg; k += stride) g_degI[k] = 0;
}

__device__ __forceinline__ bool load_edge(const void* ei_raw, int E, int N,
                                          int e, int& s, int& d) {
    long long sl, dl;
    if (g_is64) {
        const long long* ei = (const long long*)ei_raw;
        sl = ei[e]; dl = ei[(size_t)E + e];
    } else {
        const int* ei = (const int*)ei_raw;
        sl = ei[e]; dl = ei[(size_t)E + e];
    }
    if ((unsigned long long)sl >= (unsigned long long)N ||
        (unsigned long long)dl >= (unsigned long long)N) return false;
    s = (int)sl; d = (int)dl;
    return true;
}

// ---------------------------------------------------------------------------
// Kernel B: single-pass CSR build (padded rows, atomic-return slot addressing)
// BLOCK-PARTITIONED with the fp16 convert so the atomic-bound edge pass and
// the bandwidth-bound convert run on different SMs concurrently.
// ---------------------------------------------------------------------------
#define CC_BLOCKS   4096
#define EDGE_BLOCKS 2560

__global__ void build_convert_kernel(const void* __restrict__ ei_raw,
                                     const float* __restrict__ x,
                                     const float* __restrict__ Ws,
                                     const float* __restrict__ Wn,
                                     int E, int N) {
    int tid = threadIdx.x;

    if (blockIdx.x < EDGE_BLOCKS) {
        // --- edge pass: count + direct scatter into padded rows ---
        int gid = blockIdx.x * blockDim.x + tid;
        int stride = EDGE_BLOCKS * blockDim.x;
        for (int e = gid; e < E; e += stride) {
            int s, d;
            if (!load_edge(ei_raw, E, N, e, s, d)) continue;
            int ps = atomicAdd(&g_degI[s], 1);
            if (ps < CAP) g_nbr[(size_t)s * CAP + ps] = d;
            int pd = atomicAdd(&g_degI[d], 1);
            if (pd < CAP) g_nbr[(size_t)d * CAP + pd] = s;
        }
    } else {
        // --- convert partition ---
        int gid = (blockIdx.x - EDGE_BLOCKS) * blockDim.x + tid;
        int stride = (CC_BLOCKS - EDGE_BLOCKS) * blockDim.x;

        const float4* x4 = reinterpret_cast<const float4*>(x);
        uint2* xh = reinterpret_cast<uint2*>(g_xh);
        int total = N * (DIM / 4);
        for (int k = gid; k < total; k += stride) {
            float4 v = x4[k];
            uint2 o;
            o.x = h2_to_u32(__floats2half2_rn(v.x, v.y));
            o.y = h2_to_u32(__floats2half2_rn(v.z, v.w));
            xh[k] = o;
        }

        uint2* wh = reinterpret_cast<uint2*>(g_wh);
        int wtotal = 128 * 256 / 4;
        for (int k = gid; k < wtotal; k += stride) {
            int n = (k * 4) >> 8;
            int c = (k * 4) & 255;
            const float* W = (c < 128) ? (Ws + (size_t)n * 128 + c)
                                       : (Wn + (size_t)n * 128 + (c - 128));
            float4 v = *reinterpret_cast<const float4*>(W);
            uint2 o;
            o.x = h2_to_u32(__floats2half2_rn(v.x, v.y));
            o.y = h2_to_u32(__floats2half2_rn(v.z, v.w));
            wh[k] = o;
        }
    }
}

// ---------------------------------------------------------------------------
// Kernel C: gather on fp16 features. One warp per node; lane holds 4 halfs.
// ---------------------------------------------------------------------------
__global__ void gather_kernel(int N) {
    int warp = (blockIdx.x * blockDim.x + threadIdx.x) >> 5;
    int lane = threadIdx.x & 31;
    if (warp >= N) return;

    int degT = g_degI[warp];                  // true degree (normalization)
    int deg  = degT < CAP ? degT : CAP;       // readable slots
    const int* row = g_nbr + (size_t)warp * CAP;

    const uint2* xh = reinterpret_cast<const uint2*>(g_xh);
    float4 acc = make_float4(0.f, 0.f, 0.f, 0.f);

    int j = 0;
    for (; j + 8 <= deg; j += 8) {
        int n[8];
#pragma unroll
        for (int u = 0; u < 8; u++) n[u] = row[j + u];
        uint2 v[8];
#pragma unroll
        for (int u = 0; u < 8; u++) v[u] = xh[(size_t)n[u] * 32 + lane];
#pragma unroll
        for (int u = 0; u < 8; u++) {
            float2 f0 = __half22float2(u32_to_h2(v[u].x));
            float2 f1 = __half22float2(u32_to_h2(v[u].y));
            acc.x += f0.x; acc.y += f0.y; acc.z += f1.x; acc.w += f1.y;
        }
    }
    for (; j < deg; j++) {
        uint2 v = xh[(size_t)row[j] * 32 + lane];
        float2 f0 = __half22float2(u32_to_h2(v.x));
        float2 f1 = __half22float2(u32_to_h2(v.y));
        acc.x += f0.x; acc.y += f0.y; acc.z += f1.x; acc.w += f1.y;
    }

    float inv = 1.0f / fmaxf((float)degT, 1.0f);
    uint2 o;
    o.x = h2_to_u32(__floats2half2_rn(acc.x * inv, acc.y * inv));
    o.y = h2_to_u32(__floats2half2_rn(acc.z * inv, acc.w * inv));
    reinterpret_cast<uint2*>(g_ah)[(size_t)warp * 32 + lane] = o;
}

// ---------------------------------------------------------------------------
// Kernel D: fp16 mma.sync GEMM, cp.async double-buffered SMEM pipeline.
// out = relu([x_h | agg_h] @ W_h^T + bias)
// CTA: 128x128, K=256 in 8 chunks of 32 halfs. 8 warps = 2(m) x 4(n).
// ---------------------------------------------------------------------------
#define LDH 20

__device__ __forceinline__ void mma_f16(float* c, const uint32_t* a, const uint32_t* b) {
    asm volatile(
        "mma.sync.aligned.m16n8k16.row.col.f32.f16.f16.f32 "
        "{%0,%1,%2,%3}, {%4,%5,%6,%7}, {%8,%9}, {%0,%1,%2,%3};"
        : "+f"(c[0]), "+f"(c[1]), "+f"(c[2]), "+f"(c[3])
        : "r"(a[0]), "r"(a[1]), "r"(a[2]), "r"(a[3]), "r"(b[0]), "r"(b[1]));
}

__global__ __launch_bounds__(256) void gemm_mma_kernel(
    const float* __restrict__ bias,
    float* __restrict__ out,
    int N)
{
    __shared__ uint32_t As[2][128][LDH];
    __shared__ uint32_t Bs[2][128][LDH];

    int tid  = threadIdx.x;
    int wid  = tid >> 5;
    int lane = tid & 31;
    int g    = lane >> 2;
    int t    = lane & 3;
    int wm   = wid >> 2;
    int wn   = wid & 3;
    int r0   = blockIdx.x * 128;

    int arow[2], aq[2];
#pragma unroll
    for (int i = 0; i < 2; i++) {
        int idx = tid + 256 * i;
        arow[i] = idx >> 2;
        aq[i]   = idx & 3;
    }

    float acc[4][4][4];
#pragma unroll
    for (int mf = 0; mf < 4; mf++)
#pragma unroll
        for (int nf = 0; nf < 4; nf++)
#pragma unroll
            for (int i = 0; i < 4; i++) acc[mf][nf][i] = 0.f;

    auto issue = [&](int c, int buf) {
#pragma unroll
        for (int i = 0; i < 2; i++) {
            int node = r0 + arow[i];
            int kh = c * 32 + aq[i] * 8;
            const __half* srcA = (kh < DIM)
                ? (g_xh + (size_t)node * DIM + kh)
                : (g_ah + (size_t)node * DIM + (kh - DIM));
            cp16(smem_u32(&As[buf][arow[i]][aq[i] * 4]), srcA, node < N);
            cp16(smem_u32(&Bs[buf][arow[i]][aq[i] * 4]),
                 g_wh + (size_t)arow[i] * 256 + kh, true);
        }
    };

    issue(0, 0);
    asm volatile("cp.async.commit_group;" ::: "memory");

    for (int c = 0; c < 8; c++) {
        int buf = c & 1;
        if (c < 7) {
            issue(c + 1, buf ^ 1);
            asm volatile("cp.async.commit_group;" ::: "memory");
            asm volatile("cp.async.wait_group 1;" ::: "memory");
        } else {
            asm volatile("cp.async.wait_group 0;" ::: "memory");
        }
        __syncthreads();

#pragma unroll
        for (int s = 0; s < 2; s++) {
            int k0 = s * 8;
            uint32_t a[4][4];
#pragma unroll
            for (int mf = 0; mf < 4; mf++) {
                int m0 = wm * 64 + mf * 16;
                a[mf][0] = As[buf][m0 + g][k0 + t];
                a[mf][1] = As[buf][m0 + g + 8][k0 + t];
                a[mf][2] = As[buf][m0 + g][k0 + t + 4];
                a[mf][3] = As[buf][m0 + g + 8][k0 + t + 4];
            }
            uint32_t b[4][2];
#pragma unroll
            for (int nf = 0; nf < 4; nf++) {
                int n0 = wn * 32 + nf * 8;
                b[nf][0] = Bs[buf][n0 + g][k0 + t];
                b[nf][1] = Bs[buf][n0 + g][k0 + t + 4];
            }
#pragma unroll
            for (int mf = 0; mf < 4; mf++)
#pragma unroll
                for (int nf = 0; nf < 4; nf++)
                    mma_f16(acc[mf][nf], a[mf], b[nf]);
        }
        __syncthreads();
    }

    // ---- epilogue: bias + relu (fp32 out) ----
#pragma unroll
    for (int mf = 0; mf < 4; mf++) {
        int rA = r0 + wm * 64 + mf * 16 + g;
        int rB = rA + 8;
#pragma unroll
        for (int nf = 0; nf < 4; nf++) {
            int col = wn * 32 + nf * 8 + 2 * t;
            float2 bv = *reinterpret_cast<const float2*>(bias + col);
            if (rA < N) {
                float2 o;
                o.x = fmaxf(acc[mf][nf][0] + bv.x, 0.f);
                o.y = fmaxf(acc[mf][nf][1] + bv.y, 0.f);
                *reinterpret_cast<float2*>(out + (size_t)rA * DIM + col) = o;
            }
            if (rB < N) {
                float2 o;
                o.x = fmaxf(acc[mf][nf][2] + bv.x, 0.f);
                o.y = fmaxf(acc[mf][nf][3] + bv.y, 0.f);
                *reinterpret_cast<float2*>(out + (size_t)rB * DIM + col) = o;
            }
        }
    }
}

// ---------------------------------------------------------------------------
// Launch
// ---------------------------------------------------------------------------
extern "C" void kernel_launch(void* const* d_in, const int* in_sizes, int n_in,
                              void* d_out, int out_size) {
    const float* x  = (const float*)d_in[0];
    const void*  ei = d_in[1];

    int N = in_sizes[0] / DIM;          // 100000
    int E = in_sizes[1] / 2;            // 800000

    int iW = (n_in >= 6 && in_sizes[2] == 1) ? 3 : 2;
    const float* Ws   = (const float*)d_in[iW];
    const float* Wn   = (const float*)d_in[iW + 1];
    const float* bias = (const float*)d_in[iW + 2];
    float* out = (float*)d_out;

    init_probe_kernel<<<512, 256>>>((const long long*)ei, N, (long long)N);

    build_convert_kernel<<<CC_BLOCKS, 256>>>(ei, x, Ws, Wn, E, N);

    gather_kernel<<<(N + 7) / 8, 256>>>(N);

    int gblocks = (N + 127) / 128;
    gemm_mma_kernel<<<gblocks, 256>>>(bias, out, N);
}

// round 17
// speedup vs baseline: 1.5502x; 1.0549x over previous
#include <cuda_runtime.h>
#include <cuda_fp16.h>
#include <cstdint>

// ---------------------------------------------------------------------------
// GraphSAGE layer on GB300 (sm_103 baseline -> mma.sync fp16/fp32-acc)
// Single-pass padded-CSR build + fp16 gather + fp16 GEMM with SMEM-resident B.
//   agg[i] = mean over neighbors (bidirectional) of x
//   out = relu( x @ Ws^T + agg @ Wn^T + bias )   (fp32 out)
// N = 100000, in_dim = out_dim = 128, E = 800000 undirected (1.6M directed)
// ---------------------------------------------------------------------------

#define MAXN 100000
#define MAXE 800000
#define DIM  128
#define CAP  64     // neighbor slots per node; deg ~ Poisson(16), P(>=64) ~ 1e-20

__device__ __align__(16) __half g_xh [(size_t)MAXN * DIM];   // fp16 x
__device__ __align__(16) __half g_ah [(size_t)MAXN * DIM];   // fp16 agg (normalized)
__device__ __align__(16) __half g_wh [128 * 256];            // fused [Ws|Wn]
__device__ int g_degI[MAXN];
__device__ int g_nbr[(size_t)MAXN * CAP];
__device__ int g_is64;

__device__ __forceinline__ uint32_t h2_to_u32(__half2 h) {
    uint32_t u;
    *reinterpret_cast<__half2*>(&u) = h;
    return u;
}
__device__ __forceinline__ __half2 u32_to_h2(uint32_t u) {
    return *reinterpret_cast<__half2*>(&u);
}
__device__ __forceinline__ uint32_t smem_u32(const void* p) {
    return (uint32_t)__cvta_generic_to_shared(p);
}
__device__ __forceinline__ void cp16(uint32_t dst, const void* src, bool pred) {
    int sz = pred ? 16 : 0;
    asm volatile("cp.async.cg.shared.global [%0], [%1], 16, %2;"
                 :: "r"(dst), "l"(src), "r"(sz) : "memory");
}

// ---------------------------------------------------------------------------
// Kernel A: zero deg, probe edge dtype (JAX may emit int32/int64)
// ---------------------------------------------------------------------------
__global__ void init_probe_kernel(const long long* __restrict__ ei64,
                                  int n_deg, long long N) {
    int i = blockIdx.x * blockDim.x + threadIdx.x;
    int stride = gridDim.x * blockDim.x;
    if (i == 0) {
        int is64 = 1;
#pragma unroll
        for (int k = 0; k < 4; k++)
            if ((unsigned long long)ei64[k] >= (unsigned long long)N) is64 = 0;
        g_is64 = is64;
    }
    for (int k = i; k < n_deg; k += stride) g_degI[k] = 0;
}

__device__ __forceinline__ bool load_edge(const void* ei_raw, int E, int N,
                                          int e, int& s, int& d) {
    long long sl, dl;
    if (g_is64) {
        const long long* ei = (const long long*)ei_raw;
        sl = ei[e]; dl = ei[(size_t)E + e];
    } else {
        const int* ei = (const int*)ei_raw;
        sl = ei[e]; dl = ei[(size_t)E + e];
    }
    if ((unsigned long long)sl >= (unsigned long long)N ||
        (unsigned long long)dl >= (unsigned long long)N) return false;
    s = (int)sl; d = (int)dl;
    return true;
}

// ---------------------------------------------------------------------------
// Kernel B: single-pass CSR build (padded rows, atomic-return slot addressing)
// block-partitioned with the fp16 convert for real SM-level overlap.
// ---------------------------------------------------------------------------
#define CC_BLOCKS   4096
#define EDGE_BLOCKS 2560

__global__ void build_convert_kernel(const void* __restrict__ ei_raw,
                                     const float* __restrict__ x,
                                     const float* __restrict__ Ws,
                                     const float* __restrict__ Wn,
                                     int E, int N) {
    int tid = threadIdx.x;

    if (blockIdx.x < EDGE_BLOCKS) {
        int gid = blockIdx.x * blockDim.x + tid;
        int stride = EDGE_BLOCKS * blockDim.x;
        for (int e = gid; e < E; e += stride) {
            int s, d;
            if (!load_edge(ei_raw, E, N, e, s, d)) continue;
            int ps = atomicAdd(&g_degI[s], 1);
            if (ps < CAP) g_nbr[(size_t)s * CAP + ps] = d;
            int pd = atomicAdd(&g_degI[d], 1);
            if (pd < CAP) g_nbr[(size_t)d * CAP + pd] = s;
        }
    } else {
        int gid = (blockIdx.x - EDGE_BLOCKS) * blockDim.x + tid;
        int stride = (CC_BLOCKS - EDGE_BLOCKS) * blockDim.x;

        const float4* x4 = reinterpret_cast<const float4*>(x);
        uint2* xh = reinterpret_cast<uint2*>(g_xh);
        int total = N * (DIM / 4);
        for (int k = gid; k < total; k += stride) {
            float4 v = x4[k];
            uint2 o;
            o.x = h2_to_u32(__floats2half2_rn(v.x, v.y));
            o.y = h2_to_u32(__floats2half2_rn(v.z, v.w));
            xh[k] = o;
        }

        uint2* wh = reinterpret_cast<uint2*>(g_wh);
        int wtotal = 128 * 256 / 4;
        for (int k = gid; k < wtotal; k += stride) {
            int n = (k * 4) >> 8;
            int c = (k * 4) & 255;
            const float* W = (c < 128) ? (Ws + (size_t)n * 128 + c)
                                       : (Wn + (size_t)n * 128 + (c - 128));
            float4 v = *reinterpret_cast<const float4*>(W);
            uint2 o;
            o.x = h2_to_u32(__floats2half2_rn(v.x, v.y));
            o.y = h2_to_u32(__floats2half2_rn(v.z, v.w));
            wh[k] = o;
        }
    }
}

// ---------------------------------------------------------------------------
// Kernel C: gather on fp16 features. One warp per node; lane holds 4 halfs.
// ---------------------------------------------------------------------------
__global__ void gather_kernel(int N) {
    int warp = (blockIdx.x * blockDim.x + threadIdx.x) >> 5;
    int lane = threadIdx.x & 31;
    if (warp >= N) return;

    int degT = g_degI[warp];
    int deg  = degT < CAP ? degT : CAP;
    const int* row = g_nbr + (size_t)warp * CAP;

    const uint2* xh = reinterpret_cast<const uint2*>(g_xh);
    float4 acc = make_float4(0.f, 0.f, 0.f, 0.f);

    int j = 0;
    for (; j + 8 <= deg; j += 8) {
        int n[8];
#pragma unroll
        for (int u = 0; u < 8; u++) n[u] = row[j + u];
        uint2 v[8];
#pragma unroll
        for (int u = 0; u < 8; u++) v[u] = xh[(size_t)n[u] * 32 + lane];
#pragma unroll
        for (int u = 0; u < 8; u++) {
            float2 f0 = __half22float2(u32_to_h2(v[u].x));
            float2 f1 = __half22float2(u32_to_h2(v[u].y));
            acc.x += f0.x; acc.y += f0.y; acc.z += f1.x; acc.w += f1.y;
        }
    }
    for (; j < deg; j++) {
        uint2 v = xh[(size_t)row[j] * 32 + lane];
        float2 f0 = __half22float2(u32_to_h2(v.x));
        float2 f1 = __half22float2(u32_to_h2(v.y));
        acc.x += f0.x; acc.y += f0.y; acc.z += f1.x; acc.w += f1.y;
    }

    float inv = 1.0f / fmaxf((float)degT, 1.0f);
    uint2 o;
    o.x = h2_to_u32(__floats2half2_rn(acc.x * inv, acc.y * inv));
    o.y = h2_to_u32(__floats2half2_rn(acc.z * inv, acc.w * inv));
    reinterpret_cast<uint2*>(g_ah)[(size_t)warp * 32 + lane] = o;
}

// ---------------------------------------------------------------------------
// Kernel D: fp16 mma.sync GEMM. B (128x256) fully SMEM-resident; A in 4
// double-buffered chunks of 64 halfs (8 uint4/row -> 1024 uint4/chunk).
// 8 barriers total; 64 MMAs per section.
// SMEM: B [128][132]u32 (67.6KB) + A [2][128][36]u32 (36.9KB) = 102KB dynamic
// -> 2 CTAs/SM. Strides 132,36 ≡ 4 (mod 32) -> conflict-free fragment reads.
// ---------------------------------------------------------------------------
#define LDB 132
#define LDA 36
#define GEMM_SMEM ((128 * LDB + 2 * 128 * LDA) * 4)

__device__ __forceinline__ void mma_f16(float* c, const uint32_t* a, const uint32_t* b) {
    asm volatile(
        "mma.sync.aligned.m16n8k16.row.col.f32.f16.f16.f32 "
        "{%0,%1,%2,%3}, {%4,%5,%6,%7}, {%8,%9}, {%0,%1,%2,%3};"
        : "+f"(c[0]), "+f"(c[1]), "+f"(c[2]), "+f"(c[3])
        : "r"(a[0]), "r"(a[1]), "r"(a[2]), "r"(a[3]), "r"(b[0]), "r"(b[1]));
}

__global__ __launch_bounds__(256) void gemm_mma_kernel(
    const float* __restrict__ bias,
    float* __restrict__ out,
    int N)
{
    extern __shared__ uint32_t smem[];
    uint32_t* Bsm = smem;                  // [128][LDB]
    uint32_t* Asm = smem + 128 * LDB;      // [2][128][LDA]

    int tid  = threadIdx.x;
    int wid  = tid >> 5;
    int lane = tid & 31;
    int g    = lane >> 2;
    int t    = lane & 3;
    int wm   = wid >> 2;
    int wn   = wid & 3;
    int r0   = blockIdx.x * 128;

    // ---- issue full B (128 rows x 32 uint4 = 4096 uint4) ----
#pragma unroll
    for (int i = 0; i < 16; i++) {
        int idx = tid + 256 * i;           // 0..4095
        int r   = idx >> 5;                // row 0..127
        int q   = idx & 31;                // uint4 within row
        cp16(smem_u32(&Bsm[r * LDB + q * 4]), g_wh + (size_t)r * 256 + q * 8, true);
    }

    // A chunk issue: 64 halfs/row = 8 uint4/row = 1024 uint4 -> 4 per thread
    auto issueA = [&](int c, int buf) {
#pragma unroll
        for (int i = 0; i < 4; i++) {
            int idx  = tid + 256 * i;      // 0..1023
            int r    = idx >> 3;           // row 0..127
            int q    = idx & 7;            // uint4 within chunk row (0..7)
            int node = r0 + r;
            int kh   = c * 64 + q * 8;     // half index 0..255
            const __half* src = (kh < DIM)
                ? (g_xh + (size_t)node * DIM + kh)
                : (g_ah + (size_t)node * DIM + (kh - DIM));
            cp16(smem_u32(&Asm[buf * 128 * LDA + r * LDA + q * 4]), src, node < N);
        }
    };

    issueA(0, 0);
    asm volatile("cp.async.commit_group;" ::: "memory");

    float acc[4][4][4];
#pragma unroll
    for (int mf = 0; mf < 4; mf++)
#pragma unroll
        for (int nf = 0; nf < 4; nf++)
#pragma unroll
            for (int i = 0; i < 4; i++) acc[mf][nf][i] = 0.f;

    for (int c = 0; c < 4; c++) {
        int buf = c & 1;
        if (c < 3) {
            issueA(c + 1, buf ^ 1);
            asm volatile("cp.async.commit_group;" ::: "memory");
            asm volatile("cp.async.wait_group 1;" ::: "memory");
        } else {
            asm volatile("cp.async.wait_group 0;" ::: "memory");
        }
        __syncthreads();

        const uint32_t* Ab = Asm + buf * 128 * LDA;

        // ---- 4 K-steps of 16 halfs within this 64-half chunk ----
#pragma unroll
        for (int s = 0; s < 4; s++) {
            int k0 = s * 8;                          // uint32 col within chunk
            uint32_t a[4][4];
#pragma unroll
            for (int mf = 0; mf < 4; mf++) {
                int m0 = wm * 64 + mf * 16;
                a[mf][0] = Ab[(m0 + g) * LDA + k0 + t];
                a[mf][1] = Ab[(m0 + g + 8) * LDA + k0 + t];
                a[mf][2] = Ab[(m0 + g) * LDA + k0 + t + 4];
                a[mf][3] = Ab[(m0 + g + 8) * LDA + k0 + t + 4];
            }
            uint32_t b[4][2];
            int kb = c * 32 + k0;                    // uint32 col in full B row
#pragma unroll
            for (int nf = 0; nf < 4; nf++) {
                int n0 = wn * 32 + nf * 8;
                b[nf][0] = Bsm[(n0 + g) * LDB + kb + t];
                b[nf][1] = Bsm[(n0 + g) * LDB + kb + t + 4];
            }
#pragma unroll
            for (int mf = 0; mf < 4; mf++)
#pragma unroll
                for (int nf = 0; nf < 4; nf++)
                    mma_f16(acc[mf][nf], a[mf], b[nf]);
        }
        __syncthreads();   // A buffer reuse barrier
    }

    // ---- epilogue: bias + relu (fp32 out) ----
#pragma unroll
    for (int mf = 0; mf < 4; mf++) {
        int rA = r0 + wm * 64 + mf * 16 + g;
        int rB = rA + 8;
#pragma unroll
        for (int nf = 0; nf < 4; nf++) {
            int col = wn * 32 + nf * 8 + 2 * t;
            float2 bv = *reinterpret_cast<const float2*>(bias + col);
            if (rA < N) {
                float2 o;
                o.x = fmaxf(acc[mf][nf][0] + bv.x, 0.f);
                o.y = fmaxf(acc[mf][nf][1] + bv.y, 0.f);
                *reinterpret_cast<float2*>(out + (size_t)rA * DIM + col) = o;
            }
            if (rB < N) {
                float2 o;
                o.x = fmaxf(acc[mf][nf][2] + bv.x, 0.f);
                o.y = fmaxf(acc[mf][nf][3] + bv.y, 0.f);
                *reinterpret_cast<float2*>(out + (size_t)rB * DIM + col) = o;
            }
        }
    }
}

// ---------------------------------------------------------------------------
// Launch
// ---------------------------------------------------------------------------
extern "C" void kernel_launch(void* const* d_in, const int* in_sizes, int n_in,
                              void* d_out, int out_size) {
    const float* x  = (const float*)d_in[0];
    const void*  ei = d_in[1];

    int N = in_sizes[0] / DIM;          // 100000
    int E = in_sizes[1] / 2;            // 800000

    int iW = (n_in >= 6 && in_sizes[2] == 1) ? 3 : 2;
    const float* Ws   = (const float*)d_in[iW];
    const float* Wn   = (const float*)d_in[iW + 1];
    const float* bias = (const float*)d_in[iW + 2];
    float* out = (float*)d_out;

    cudaFuncSetAttribute(gemm_mma_kernel,
                         cudaFuncAttributeMaxDynamicSharedMemorySize, GEMM_SMEM);

    init_probe_kernel<<<512, 256>>>((const long long*)ei, N, (long long)N);

    build_convert_kernel<<<CC_BLOCKS, 256>>>(ei, x, Ws, Wn, E, N);

    gather_kernel<<<(N + 7) / 8, 256>>>(N);

    int gblocks = (N + 127) / 128;
    gemm_mma_kernel<<<gblocks, 256, GEMM_SMEM>>>(bias, out, N);
}